// round 14
// baseline (speedup 1.0000x reference)
#include <cuda_runtime.h>

// LSTMNet: 3-layer LSTM (H=6, input=1), B=8192, T=512, FC head on final h2.
// Round 14: layer-wavefront with h-state in SMEM ping-pong buffers.
// Iteration n: l2(n-2), l1(n-1), l0(n) -- all inputs read from the OTHER
// parity buffer (written last iteration), so the three bodies share no
// registers -> ptxas can interleave the chains (R7/R12 failed because
// register-resident h arrays created WAR deps). SHFL eliminated (6 LDS +
// 3 STS per iter replace 18 SHFL). Column-pair weights (R10), tanh cell (R11).

#define HD 6
#define TT 512
#define PK 164                 // floats per lane-k slice; 656B stride, conflict-free
#define WPB 12
#define TPB (WPB * 32)
__device__ float g_packk[6 * PK];

// per-k slice layout (floats):
//   0:  b0 packed (b,0) x4       8: wx0 packed (w,0) x4
//  16:  Whh0 col-pairs (m*4+g)*2 -> (w[g][2m],w[g][2m+1])  [16..40)
//  40:  b1 packed (b,0) x4      48: Wih1 pairs [48..72)    72: Whh1 [72..96)
//  96:  b2 packed (b,0) x4     104: Wih2 [104..128)       128: Whh2 [128..152)
// 152: fc_w[k] (pre-halved)  153: fc_b
// scales: sigmoid rows (i,f,o) x0.5 (tanh half-angle); tanh row (g) x1.0.
// h-consuming weights extra x0.5 (h stored doubled: 2h).

__global__ void prep_kernel(
    const float* __restrict__ Wih0, const float* __restrict__ Whh0,
    const float* __restrict__ bih0, const float* __restrict__ bhh0,
    const float* __restrict__ Wih1, const float* __restrict__ Whh1,
    const float* __restrict__ bih1, const float* __restrict__ bhh1,
    const float* __restrict__ Wih2, const float* __restrict__ Whh2,
    const float* __restrict__ bih2, const float* __restrict__ bhh2,
    const float* __restrict__ fcw, const float* __restrict__ fcb)
{
    int tid = threadIdx.x;
    if (tid < 24) {
        int k = tid / 4, g = tid % 4;
        float s  = (g == 2) ? 1.0f : 0.5f;
        float sh = s * 0.5f;                  // doubled-h compensation
        int row = g * HD + k;                 // PyTorch gate order i,f,g,o
        float* p = g_packk + k * PK;
        p[0  + 2*g] = (bih0[row] + bhh0[row]) * s;  p[1  + 2*g] = 0.f;
        p[8  + 2*g] = Wih0[row] * s;                p[9  + 2*g] = 0.f;
        p[40 + 2*g] = (bih1[row] + bhh1[row]) * s;  p[41 + 2*g] = 0.f;
        p[96 + 2*g] = (bih2[row] + bhh2[row]) * s;  p[97 + 2*g] = 0.f;
        for (int m = 0; m < 3; m++) {
            int o = (m * 4 + g) * 2;
            p[16  + o] = Whh0[row*HD + 2*m] * sh;  p[17  + o] = Whh0[row*HD + 2*m+1] * sh;
            p[48  + o] = Wih1[row*HD + 2*m] * sh;  p[49  + o] = Wih1[row*HD + 2*m+1] * sh;
            p[72  + o] = Whh1[row*HD + 2*m] * sh;  p[73  + o] = Whh1[row*HD + 2*m+1] * sh;
            p[104 + o] = Wih2[row*HD + 2*m] * sh;  p[105 + o] = Wih2[row*HD + 2*m+1] * sh;
            p[128 + o] = Whh2[row*HD + 2*m] * sh;  p[129 + o] = Whh2[row*HD + 2*m+1] * sh;
        }
    }
    if (tid < 6) {
        g_packk[tid * PK + 152] = fcw[tid] * 0.5f;
        g_packk[tid * PK + 153] = fcb[0];
    }
}

typedef unsigned long long ull;

__device__ __forceinline__ void fma2(ull& d, ull a, ull b, ull c) {
    asm("fma.rn.f32x2 %0, %1, %2, %3;" : "=l"(d) : "l"(a), "l"(b), "l"(c));
}
__device__ __forceinline__ ull pack2(float x, float y) {
    ull d; asm("mov.b64 %0, {%1, %2};" : "=l"(d) : "f"(x), "f"(y)); return d;
}
__device__ __forceinline__ float hadd2(ull v) {
    float x, y; asm("mov.b64 {%0, %1}, %2;" : "=f"(x), "=f"(y) : "l"(v));
    return x + y;
}
__device__ __forceinline__ float tanh_ap(float x) {
    float y; asm("tanh.approx.f32 %0, %1;" : "=f"(y) : "f"(x)); return y;
}

// scalar gate pre-activations (zi/2, zf/2, zg, zo/2); c true; h returned doubled
__device__ __forceinline__ void cell_s(float ai, float af, float ag, float ao,
                                       float& c, float& h2x)
{
    float ti = tanh_ap(ai);
    float tf = tanh_ap(af);
    float tg = tanh_ap(ag);
    float to = tanh_ap(ao);
    float A  = fmaf(tf, c, c);        // 2f*c
    float Bv = fmaf(ti, tg, tg);      // 2i*g
    c = (A + Bv) * 0.5f;
    float th = tanh_ap(c);
    h2x = fmaf(to, th, th);           // 2h
}

struct HV { ull p0, p1, p2; };        // (h0,h1),(h2,h3),(h4,h5)

// h buffer: [par(2)][layer(3)][warp(WPB)][sub(5)][12 floats (6 used, 48B slot)]
#define HSUB   12
#define HWARP  (5 * HSUB)             // 60
#define HLAYER (WPB * HWARP)          // 720
#define HPAR   (3 * HLAYER)           // 2160
#define HBUF_N (2 * HPAR)             // 4320 floats = 17280 B

#define LOADHV(V, P)                                                    \
    {   ulonglong2 t_ = *(const ulonglong2*)(P);                        \
        (V).p0 = t_.x; (V).p1 = t_.y;                                   \
        (V).p2 = *(const ull*)((P) + 4); }

// matvec over 2 packed matrices + bias init + cell + guarded store.
// W: ulonglong2*, [2m]=(i,f) pair m, [2m+1]=(g,o) pair m.
#define MVBODY(WIN, VA, WREC, VB, BP, CC, HN, WP)                       \
    {   ull t0_, t1_, t2_, t3_;                                         \
        { ulonglong2 wa = (WIN)[0], wb = (WIN)[1];                      \
          fma2(t0_, wa.x, (VA).p0, (BP)[0]);                            \
          fma2(t1_, wa.y, (VA).p0, (BP)[1]);                            \
          fma2(t2_, wb.x, (VA).p0, (BP)[2]);                            \
          fma2(t3_, wb.y, (VA).p0, (BP)[3]); }                          \
        { ulonglong2 wa = (WIN)[2], wb = (WIN)[3];                      \
          fma2(t0_, wa.x, (VA).p1, t0_); fma2(t1_, wa.y, (VA).p1, t1_); \
          fma2(t2_, wb.x, (VA).p1, t2_); fma2(t3_, wb.y, (VA).p1, t3_); } \
        { ulonglong2 wa = (WIN)[4], wb = (WIN)[5];                      \
          fma2(t0_, wa.x, (VA).p2, t0_); fma2(t1_, wa.y, (VA).p2, t1_); \
          fma2(t2_, wb.x, (VA).p2, t2_); fma2(t3_, wb.y, (VA).p2, t3_); } \
        { ulonglong2 wa = (WREC)[0], wb = (WREC)[1];                    \
          fma2(t0_, wa.x, (VB).p0, t0_); fma2(t1_, wa.y, (VB).p0, t1_); \
          fma2(t2_, wb.x, (VB).p0, t2_); fma2(t3_, wb.y, (VB).p0, t3_); } \
        { ulonglong2 wa = (WREC)[2], wb = (WREC)[3];                    \
          fma2(t0_, wa.x, (VB).p1, t0_); fma2(t1_, wa.y, (VB).p1, t1_); \
          fma2(t2_, wb.x, (VB).p1, t2_); fma2(t3_, wb.y, (VB).p1, t3_); } \
        { ulonglong2 wa = (WREC)[4], wb = (WREC)[5];                    \
          fma2(t0_, wa.x, (VB).p2, t0_); fma2(t1_, wa.y, (VB).p2, t1_); \
          fma2(t2_, wb.x, (VB).p2, t2_); fma2(t3_, wb.y, (VB).p2, t3_); } \
        cell_s(hadd2(t0_), hadd2(t1_), hadd2(t2_), hadd2(t3_), CC, HN); \
        if (act) *(WP) = HN;                                            \
    }

__global__ void __launch_bounds__(TPB, 1)
lstm6_kernel(const float* __restrict__ x, float* __restrict__ out, int B)
{
    __shared__ __align__(16) float sw[6 * PK];
    __shared__ __align__(16) float hbuf[HBUF_N];
    for (int i = threadIdx.x; i < 6 * PK; i += TPB) sw[i] = g_packk[i];

    int wwid = threadIdx.x >> 5;
    int wid  = blockIdx.x * WPB + wwid;
    int lane = threadIdx.x & 31;

    int sub = lane / HD;                            // 0..4 active, 5 = spare
    int k   = lane - sub * HD;
    bool act = (sub < 5);
    int sv  = act ? sub : 0;
    int sb  = sv * HD;                              // shuffle base (FC only)
    int elem = wid * 5 + sv;
    bool store_ok = act && (elem < B) && (k == 0);
    if (elem >= B) elem = B - 1;                    // clamp loads only

    // zero own warp's h regions (both parities, all layers)
    {
        float* z = hbuf + wwid * HWARP + sv * HSUB + k;
        if (act) {
#pragma unroll
            for (int par = 0; par < 2; par++)
#pragma unroll
                for (int L = 0; L < 3; L++)
                    z[par * HPAR + L * HLAYER] = 0.f;
        }
    }
    __syncthreads();
    if (wid * 5 >= B) return;                       // warp-uniform exit

    const float* pk = sw + k * PK;
    const ull* s8 = reinterpret_cast<const ull*>(pk);

    // hoisted constants
    ull b0p[4], wxp[4], b1p[4], b2p[4];
#pragma unroll
    for (int g = 0; g < 4; g++) {
        b0p[g] = s8[0  + g];
        wxp[g] = s8[4  + g];
        b1p[g] = s8[20 + g];
        b2p[g] = s8[48 + g];
    }
    float fcwk = pk[152], fcbv = pk[153];

    const ulonglong2* w0c   = reinterpret_cast<const ulonglong2*>(pk + 16);
    const ulonglong2* w1in  = reinterpret_cast<const ulonglong2*>(pk + 48);
    const ulonglong2* w1rec = reinterpret_cast<const ulonglong2*>(pk + 72);
    const ulonglong2* w2in  = reinterpret_cast<const ulonglong2*>(pk + 104);
    const ulonglong2* w2rec = reinterpret_cast<const ulonglong2*>(pk + 128);

    // h buffer pointers: read base (par, L0) and per-lane write base
    float* r0 = hbuf + wwid * HWARP + sv * HSUB;            // par0, L0
    float* r1 = r0 + HPAR;                                  // par1, L0
    float* wp0 = r0 + k;                                    // par0 write (lane k)
    float* wp1 = wp0 + HPAR;                                // par1 write

    const float* xp = x + (size_t)elem * TT;

    float c0 = 0.f, c1 = 0.f, c2 = 0.f, h2own = 0.f;

    // ITER: reads parity RB (written last iter), writes WB.
#define ITER(RB, WB, D0, D1, D2, XT)                                    \
    {   __syncwarp();                                                   \
        HV v0, v1, v2;                                                  \
        if (D0 || D1) LOADHV(v0, (RB));                                 \
        if (D1 || D2) LOADHV(v1, (RB) + HLAYER);                        \
        if (D2)       LOADHV(v2, (RB) + 2 * HLAYER);                    \
        if (D2) {                                                       \
            MVBODY(w2in, v1, w2rec, v2, b2p, c2, h2own,                 \
                   (WB) + 2 * HLAYER);                                  \
        }                                                               \
        if (D1) {                                                       \
            float h1n_;                                                 \
            MVBODY(w1in, v0, w1rec, v1, b1p, c1, h1n_,                  \
                   (WB) + HLAYER);                                      \
        }                                                               \
        if (D0) {                                                       \
            ull xx_ = pack2((XT), (XT));                                \
            ull t0_, t1_, t2_, t3_;                                     \
            fma2(t0_, wxp[0], xx_, b0p[0]);                             \
            fma2(t1_, wxp[1], xx_, b0p[1]);                             \
            fma2(t2_, wxp[2], xx_, b0p[2]);                             \
            fma2(t3_, wxp[3], xx_, b0p[3]);                             \
            { ulonglong2 wa = w0c[0], wb = w0c[1];                      \
              fma2(t0_, wa.x, v0.p0, t0_); fma2(t1_, wa.y, v0.p0, t1_); \
              fma2(t2_, wb.x, v0.p0, t2_); fma2(t3_, wb.y, v0.p0, t3_); } \
            { ulonglong2 wa = w0c[2], wb = w0c[3];                      \
              fma2(t0_, wa.x, v0.p1, t0_); fma2(t1_, wa.y, v0.p1, t1_); \
              fma2(t2_, wb.x, v0.p1, t2_); fma2(t3_, wb.y, v0.p1, t3_); } \
            { ulonglong2 wa = w0c[4], wb = w0c[5];                      \
              fma2(t0_, wa.x, v0.p2, t0_); fma2(t1_, wa.y, v0.p2, t1_); \
              fma2(t2_, wb.x, v0.p2, t2_); fma2(t3_, wb.y, v0.p2, t3_); } \
            float h0n_;                                                 \
            cell_s(hadd2(t0_), hadd2(t1_), hadd2(t2_), hadd2(t3_),      \
                   c0, h0n_);                                           \
            if (act) *(WB) = h0n_;                                      \
        }                                                               \
    }

    // wavefront fill: n=0 (l0 only), n=1 (l1, l0)
    {
        float xa = __ldg(xp + 0);
        float xb = __ldg(xp + 1);
        ITER(r0, wp1, 1, 0, 0, xa);     // n=0: read par0(zeros), write par1
        ITER(r1, wp0, 1, 1, 0, xb);     // n=1: read par1, write par0
    }

    // main wavefront: n = 2..511 (255 unrolled pairs)
    const float* xr = xp + 2;
#pragma unroll 1
    for (int gi = 0; gi < 255; gi++) {
        float xa = __ldg(xr);
        float xb = __ldg(xr + 1);
        xr += 2;
        ITER(r0, wp1, 1, 1, 1, xa);     // n even: read par0, write par1
        ITER(r1, wp0, 1, 1, 1, xb);     // n odd:  read par1, write par0
    }

    // drain: n=512 (l2(510), l1(511)), n=513 (l2(511))
    ITER(r0, wp1, 0, 1, 1, 0.f);
    ITER(r1, wp0, 0, 0, 1, 0.f);

    // FC head: out[e] = sum_k (2h2[k])*(fc_w[k]/2) + fc_b
    float r = h2own * fcwk;
    float s = fcbv;
#pragma unroll
    for (int j = 0; j < HD; j++)
        s += __shfl_sync(0xffffffffu, r, sb + j);
    if (store_ok) out[elem] = s;

#undef ITER
}

extern "C" void kernel_launch(void* const* d_in, const int* in_sizes, int n_in,
                              void* d_out, int out_size)
{
    const float* x = (const float*)d_in[0];
    int B = in_sizes[0] / TT;                  // 8192
    int warps  = (B + 4) / 5;                  // 1639
    int blocks = (warps + WPB - 1) / WPB;      // 137

    prep_kernel<<<1, 64>>>(
        (const float*)d_in[1],  (const float*)d_in[2],
        (const float*)d_in[3],  (const float*)d_in[4],
        (const float*)d_in[5],  (const float*)d_in[6],
        (const float*)d_in[7],  (const float*)d_in[8],
        (const float*)d_in[9],  (const float*)d_in[10],
        (const float*)d_in[11], (const float*)d_in[12],
        (const float*)d_in[13], (const float*)d_in[14]);

    lstm6_kernel<<<blocks, TPB>>>(x, (float*)d_out, B);
}

// round 15
// speedup vs baseline: 1.6402x; 1.6402x over previous
#include <cuda_runtime.h>

// LSTMNet: 3-layer LSTM (H=6, input=1), B=8192, T=512, FC head on final h2.
// Round 15: R11 (tanh cell, 205.9us champion) + TWO scalar element-streams
// per lane (10 elems/warp). Weight LDS + loop overhead amortized 2x; per-warp
// ILP=2 independent recurrences. 820 warps -> 137 blocks x 6 warps (TPB=192),
// single wave. Scalar (non-packed) state keeps regs under the 255 ceiling
// (R6/R8/R9 failed there with packed state / ex2-era transients).

#define HD 6
#define TT 512
#define PK 164                 // floats per lane-k slice; 656B stride, conflict-free
#define WPB 6
#define TPB (WPB * 32)
#define EPW 10                 // elements per warp (5 subgroups x 2 streams)
__device__ float g_packk[6 * PK];

// per-k slice layout (floats):
//   0: b0[4] (i,f,g,o)   4: wx0[4]   8+4j: Whh0 col j
//  32: b1   36+4j: Wih1 col j   60+4j: Whh1 col j
//  84: b2   88+4j: Wih2 col j  112+4j: Whh2 col j
// 136: fc_w[k] (pre-halved)  137: fc_b
// scales: rows i,f,o: x0.5 (tanh half-angle); row g: x1.0.
// h-consuming weights additionally x0.5 (stored h is doubled: 2h).

__global__ void prep_kernel(
    const float* __restrict__ Wih0, const float* __restrict__ Whh0,
    const float* __restrict__ bih0, const float* __restrict__ bhh0,
    const float* __restrict__ Wih1, const float* __restrict__ Whh1,
    const float* __restrict__ bih1, const float* __restrict__ bhh1,
    const float* __restrict__ Wih2, const float* __restrict__ Whh2,
    const float* __restrict__ bih2, const float* __restrict__ bhh2,
    const float* __restrict__ fcw, const float* __restrict__ fcb)
{
    int tid = threadIdx.x;
    if (tid < 24) {
        int k = tid / 4, g = tid % 4;
        float s  = (g == 2) ? 1.0f : 0.5f;    // pre-activation scale
        float sh = s * 0.5f;                  // + compensation for doubled h
        int row = g * HD + k;                 // PyTorch gate order i,f,g,o
        float* p = g_packk + k * PK;
        p[0 + g]  = (bih0[row] + bhh0[row]) * s;
        p[4 + g]  = Wih0[row] * s;            // x input (not doubled)
        p[32 + g] = (bih1[row] + bhh1[row]) * s;
        p[84 + g] = (bih2[row] + bhh2[row]) * s;
        for (int j = 0; j < HD; j++) {
            p[8   + j * 4 + g] = Whh0[row * HD + j] * sh;
            p[36  + j * 4 + g] = Wih1[row * HD + j] * sh;
            p[60  + j * 4 + g] = Whh1[row * HD + j] * sh;
            p[88  + j * 4 + g] = Wih2[row * HD + j] * sh;
            p[112 + j * 4 + g] = Whh2[row * HD + j] * sh;
        }
    }
    if (tid < 6) {
        g_packk[tid * PK + 136] = fcw[tid] * 0.5f;   // consumes doubled h2
        g_packk[tid * PK + 137] = fcb[0];
    }
}

typedef unsigned long long ull;

// ---- f32x2 + fast-math primitives ----
__device__ __forceinline__ void fma2(ull& d, ull a, ull b, ull c) {
    asm("fma.rn.f32x2 %0, %1, %2, %3;" : "=l"(d) : "l"(a), "l"(b), "l"(c));
}
__device__ __forceinline__ void mul2(ull& d, ull a, ull b) {
    asm("mul.rn.f32x2 %0, %1, %2;" : "=l"(d) : "l"(a), "l"(b));
}
__device__ __forceinline__ void add2(ull& d, ull a, ull b) {
    asm("add.rn.f32x2 %0, %1, %2;" : "=l"(d) : "l"(a), "l"(b));
}
__device__ __forceinline__ ull pack2(float x, float y) {
    ull d; asm("mov.b64 %0, {%1, %2};" : "=l"(d) : "f"(x), "f"(y)); return d;
}
__device__ __forceinline__ void unpack2(float& x, float& y, ull v) {
    asm("mov.b64 {%0, %1}, %2;" : "=f"(x), "=f"(y) : "l"(v));
}
__device__ __forceinline__ float tanh_ap(float x) {
    float y; asm("tanh.approx.f32 %0, %1;" : "=f"(y) : "f"(x)); return y;
}

// aif = (zi/2, zf/2), ago = (zg, zo/2)  [h-doubling already folded in weights]
// outputs: c (true cell state), h2x = 2*h (doubled hidden)
__device__ __forceinline__ void cell(ull aif, ull ago, float& c, float& h2x) {
    float ai, af, ag, ao;
    unpack2(ai, af, aif);
    unpack2(ag, ao, ago);
    float ti = tanh_ap(ai);
    float tf = tanh_ap(af);
    float tg = tanh_ap(ag);
    float to = tanh_ap(ao);
    float A  = fmaf(tf, c, c);        // 2f*c
    float Bv = fmaf(ti, tg, tg);      // 2i*g
    c = (A + Bv) * 0.5f;
    float th = tanh_ap(c);
    h2x = fmaf(to, th, th);           // 2h
}

// 12-col matvec for TWO streams; weights loaded once, used twice.
__device__ __forceinline__ void matvec12x2(const ulonglong2* __restrict__ w2,
    const float vinA[HD], const float vrecA[HD],
    const float vinB[HD], const float vrecB[HD],
    ull bif, ull bgo,
    ull& aifA, ull& agoA, ull& aifB, ull& agoB)
{
    ull a0A, a1A, q0A, q1A, a0B, a1B, q0B, q1B;
    {   ulonglong2 w = w2[0];
        ull vA = pack2(vinA[0], vinA[0]);
        ull vB = pack2(vinB[0], vinB[0]);
        fma2(a0A, w.x, vA, bif); fma2(a1A, w.y, vA, bgo);
        fma2(a0B, w.x, vB, bif); fma2(a1B, w.y, vB, bgo); }
#pragma unroll
    for (int j = 1; j < HD; j++) {
        ulonglong2 w = w2[j];
        ull vA = pack2(vinA[j], vinA[j]);
        ull vB = pack2(vinB[j], vinB[j]);
        fma2(a0A, w.x, vA, a0A); fma2(a1A, w.y, vA, a1A);
        fma2(a0B, w.x, vB, a0B); fma2(a1B, w.y, vB, a1B);
    }
    {   ulonglong2 w = w2[6];
        ull vA = pack2(vrecA[0], vrecA[0]);
        ull vB = pack2(vrecB[0], vrecB[0]);
        mul2(q0A, w.x, vA); mul2(q1A, w.y, vA);
        mul2(q0B, w.x, vB); mul2(q1B, w.y, vB); }
#pragma unroll
    for (int j = 1; j < HD; j++) {
        ulonglong2 w = w2[6 + j];
        ull vA = pack2(vrecA[j], vrecA[j]);
        ull vB = pack2(vrecB[j], vrecB[j]);
        fma2(q0A, w.x, vA, q0A); fma2(q1A, w.y, vA, q1A);
        fma2(q0B, w.x, vB, q0B); fma2(q1B, w.y, vB, q1B);
    }
    add2(aifA, a0A, q0A); add2(agoA, a1A, q1A);
    add2(aifB, a0B, q0B); add2(agoB, a1B, q1B);
}

__global__ void __launch_bounds__(TPB, 1)
lstm6_kernel(const float* __restrict__ x, float* __restrict__ out, int B)
{
    __shared__ __align__(16) float sw[6 * PK];
    for (int i = threadIdx.x; i < 6 * PK; i += TPB) sw[i] = g_packk[i];
    __syncthreads();

    int wid  = blockIdx.x * WPB + (threadIdx.x >> 5);
    int lane = threadIdx.x & 31;
    if (wid * EPW >= B) return;                     // warp-uniform exit

    int sub = lane / HD;                            // 0..4 active, 5 = spare
    int k   = lane - sub * HD;
    int sb  = (sub < 5) ? sub * HD : 0;             // shuffle base
    int sv  = (sub < 5) ? sub : 0;

    int eA = wid * EPW + sv;                        // stream A element
    int eB = eA + 5;                                // stream B element
    bool okA = (sub < 5) && (eA < B) && (k == 0);
    bool okB = (sub < 5) && (eB < B) && (k == 0);
    int lA = (eA < B) ? eA : (B - 1);               // clamp loads only
    int lB = (eB < B) ? eB : (B - 1);

    const float* pk = sw + k * PK;
    const ull* pk8 = reinterpret_cast<const ull*>(pk);

    // hoist biases + layer-0 x-weights + fc only
    ull b0if = pk8[0],  b0go = pk8[1];
    ull wxif = pk8[2],  wxgo = pk8[3];
    ull b1if = pk8[16], b1go = pk8[17];
    ull b2if = pk8[42], b2go = pk8[43];
    float fcwk = pk[136], fcbv = pk[137];

    const ulonglong2* w0c = reinterpret_cast<const ulonglong2*>(pk8 + 4);  // 6 cols
    const ulonglong2* w1c = reinterpret_cast<const ulonglong2*>(pk8 + 18); // 12 cols
    const ulonglong2* w2c = reinterpret_cast<const ulonglong2*>(pk8 + 44); // 12 cols

    const float4* xpA = reinterpret_cast<const float4*>(x + (size_t)lA * TT);
    const float4* xpB = reinterpret_cast<const float4*>(x + (size_t)lB * TT);

    float h0A[HD], h1A[HD], h2A[HD], h0B[HD], h1B[HD], h2B[HD];
    float c0A = 0.f, c1A = 0.f, c2A = 0.f, h2ownA = 0.f;
    float c0B = 0.f, c1B = 0.f, c2B = 0.f, h2ownB = 0.f;
#pragma unroll
    for (int j = 0; j < HD; j++) {
        h0A[j] = h1A[j] = h2A[j] = 0.f;
        h0B[j] = h1B[j] = h2B[j] = 0.f;
    }

#pragma unroll 1
    for (int t4 = 0; t4 < TT / 4; t4++) {
        float4 xqA = __ldg(xpA + t4);
        float4 xqB = __ldg(xpB + t4);
#pragma unroll
        for (int u = 0; u < 4; u++) {
            float xtA = (u == 0) ? xqA.x : (u == 1) ? xqA.y : (u == 2) ? xqA.z : xqA.w;
            float xtB = (u == 0) ? xqB.x : (u == 1) ? xqB.y : (u == 2) ? xqB.z : xqB.w;

            // ---- layer 0: b0 + wx*x + Whh0 @ h0 (2 chains x 2 streams) ----
            ull aifA, agoA, aifB, agoB;
            {
                ull xxA = pack2(xtA, xtA), xxB = pack2(xtB, xtB);
                ull a0A, a1A, q0A, q1A, a0B, a1B, q0B, q1B;
                fma2(a0A, wxif, xxA, b0if); fma2(a1A, wxgo, xxA, b0go);
                fma2(a0B, wxif, xxB, b0if); fma2(a1B, wxgo, xxB, b0go);
#pragma unroll
                for (int j = 0; j < 3; j++) {
                    ulonglong2 w = w0c[j];
                    ull vA = pack2(h0A[j], h0A[j]);
                    ull vB = pack2(h0B[j], h0B[j]);
                    fma2(a0A, w.x, vA, a0A); fma2(a1A, w.y, vA, a1A);
                    fma2(a0B, w.x, vB, a0B); fma2(a1B, w.y, vB, a1B);
                }
                {   ulonglong2 w = w0c[3];
                    ull vA = pack2(h0A[3], h0A[3]);
                    ull vB = pack2(h0B[3], h0B[3]);
                    mul2(q0A, w.x, vA); mul2(q1A, w.y, vA);
                    mul2(q0B, w.x, vB); mul2(q1B, w.y, vB); }
#pragma unroll
                for (int j = 4; j < HD; j++) {
                    ulonglong2 w = w0c[j];
                    ull vA = pack2(h0A[j], h0A[j]);
                    ull vB = pack2(h0B[j], h0B[j]);
                    fma2(q0A, w.x, vA, q0A); fma2(q1A, w.y, vA, q1A);
                    fma2(q0B, w.x, vB, q0B); fma2(q1B, w.y, vB, q1B);
                }
                add2(aifA, a0A, q0A); add2(agoA, a1A, q1A);
                add2(aifB, a0B, q0B); add2(agoB, a1B, q1B);
            }
            float h0nA, h0nB;
            cell(aifA, agoA, c0A, h0nA);
            cell(aifB, agoB, c0B, h0nB);
#pragma unroll
            for (int j = 0; j < HD; j++) {
                h0A[j] = __shfl_sync(0xffffffffu, h0nA, sb + j);
                h0B[j] = __shfl_sync(0xffffffffu, h0nB, sb + j);
            }

            // ---- layer 1 ----
            float h1nA, h1nB;
            matvec12x2(w1c, h0A, h1A, h0B, h1B, b1if, b1go,
                       aifA, agoA, aifB, agoB);
            cell(aifA, agoA, c1A, h1nA);
            cell(aifB, agoB, c1B, h1nB);
#pragma unroll
            for (int j = 0; j < HD; j++) {
                h1A[j] = __shfl_sync(0xffffffffu, h1nA, sb + j);
                h1B[j] = __shfl_sync(0xffffffffu, h1nB, sb + j);
            }

            // ---- layer 2 ----
            matvec12x2(w2c, h1A, h2A, h1B, h2B, b2if, b2go,
                       aifA, agoA, aifB, agoB);
            cell(aifA, agoA, c2A, h2ownA);
            cell(aifB, agoB, c2B, h2ownB);
#pragma unroll
            for (int j = 0; j < HD; j++) {
                h2A[j] = __shfl_sync(0xffffffffu, h2ownA, sb + j);
                h2B[j] = __shfl_sync(0xffffffffu, h2ownB, sb + j);
            }
        }
    }

    // FC head per stream: out[e] = sum_k (2h2[k])*(fc_w[k]/2) + fc_b
    float rA = h2ownA * fcwk;
    float rB = h2ownB * fcwk;
    float sA = fcbv, sB = fcbv;
#pragma unroll
    for (int j = 0; j < HD; j++) {
        sA += __shfl_sync(0xffffffffu, rA, sb + j);
        sB += __shfl_sync(0xffffffffu, rB, sb + j);
    }
    if (okA) out[eA] = sA;
    if (okB) out[eB] = sB;
}

extern "C" void kernel_launch(void* const* d_in, const int* in_sizes, int n_in,
                              void* d_out, int out_size)
{
    const float* x = (const float*)d_in[0];
    int B = in_sizes[0] / TT;                  // 8192
    int warps  = (B + EPW - 1) / EPW;          // 820
    int blocks = (warps + WPB - 1) / WPB;      // 137

    prep_kernel<<<1, 64>>>(
        (const float*)d_in[1],  (const float*)d_in[2],
        (const float*)d_in[3],  (const float*)d_in[4],
        (const float*)d_in[5],  (const float*)d_in[6],
        (const float*)d_in[7],  (const float*)d_in[8],
        (const float*)d_in[9],  (const float*)d_in[10],
        (const float*)d_in[11], (const float*)d_in[12],
        (const float*)d_in[13], (const float*)d_in[14]);

    lstm6_kernel<<<blocks, TPB>>>(x, (float*)d_out, B);
}